// round 14
// baseline (speedup 1.0000x reference)
#include <cuda_runtime.h>
#include <cuda_fp16.h>
#include <cuda_bf16.h>
#include <cstdint>

// Problem constants
#define B_BATCH 64
#define T_LEN   2048
#define F_DIM   256
#define BT      (B_BATCH * T_LEN)   // 131072
#define NSB     (BT / 256)          // 512 super-blocks of 256 rows
#define NTASK   1024                // 16 chunks x 64 batches (wsum phase)

// ---------------------------------------------------------------------------
// Scratch (no allocations allowed -> device globals)
// ---------------------------------------------------------------------------
__device__ __half g_Wh[F_DIM * F_DIM];    // W^T fp16: g_Wh[g*256+f] = W[f][g]
__device__ __half g_xh[(long)BT * F_DIM]; // x in fp16 (written in ait staging)
__device__ float g_aitp[2][BT];           // per-half partial ait
__device__ float g_sum[B_BATCH];
__device__ float g_part[16 * B_BATCH * F_DIM];
__device__ unsigned g_cnt[B_BATCH];       // wsum completion tickets
__device__ unsigned g_bar;                // monotonic device-wide barrier

__device__ __forceinline__ uint32_t smem_u32(const void* p) {
    uint32_t a;
    asm("{ .reg .u64 t; cvta.to.shared.u64 t, %1; cvt.u32.u64 %0, t; }" : "=r"(a) : "l"(p));
    return a;
}
__device__ __forceinline__ void cp16(uint32_t dst, const void* src) {
    asm volatile("cp.async.cg.shared.global [%0], [%1], 16;" :: "r"(dst), "l"(src));
}
#define CP_COMMIT()  asm volatile("cp.async.commit_group;" ::: "memory")
#define CP_WAIT(n)   asm volatile("cp.async.wait_group %0;" :: "n"(n) : "memory")
__device__ __forceinline__ float tanh_fast(float z) {
    float r;
    asm("tanh.approx.f32 %0, %1;" : "=f"(r) : "f"(z));
    return r;
}

// Device-wide barrier: monotonic counter, safe across graph replays.
// Requires all gridDim.x CTAs co-resident (guaranteed: 1 CTA/SM, grid<=SMs).
__device__ __forceinline__ void global_barrier() {
    __syncthreads();
    if (threadIdx.x == 0) {
        __threadfence();
        unsigned t = atomicAdd(&g_bar, 1u);
        unsigned target = (t / gridDim.x + 1u) * gridDim.x;
        unsigned v;
        do {
            asm volatile("ld.global.acquire.gpu.u32 %0, [%1];" : "=r"(v) : "l"(&g_bar));
            if (v < target) __nanosleep(128);
        } while (v < target);
    }
    __syncthreads();
}

// ---------------------------------------------------------------------------
// Phase 0: W -> fp16, transposed to [g][f] (K-major for the B operand)
// ---------------------------------------------------------------------------
__global__ void __launch_bounds__(256) k_wt(const float* __restrict__ W)
{
    __shared__ float tile[32][33];
    const int tx = threadIdx.x, ty = threadIdx.y;
    const int gx = blockIdx.x * 32, gy = blockIdx.y * 32;
    #pragma unroll
    for (int j = ty; j < 32; j += 8)
        tile[j][tx] = W[(gy + j) * F_DIM + gx + tx];
    __syncthreads();
    #pragma unroll
    for (int j = ty; j < 32; j += 8)
        g_Wh[(gx + j) * F_DIM + gy + tx] = __float2half_rn(tile[tx][j]);
}

// ---------------------------------------------------------------------------
// Fused persistent kernel:
//   Phase A (ait): N-split fp16 mma, single-sync overlapped pipeline
//     (identical to round-13 k_ait; writes g_aitp + fp16 x to g_xh).
//   -- device-wide barrier --
//   Phase B (softsum): CTAs 0..63 compute g_sum[b]; reset tickets.
//   -- device-wide barrier --
//   Phase C (wsum): 1024 (chunk,b) tasks strided over CTAs, reading g_xh
//     (hot in L2 from phase A); last CTA per b does the fixed-order 16-way
//     reduction -> out. Deterministic.
// ---------------------------------------------------------------------------
#define SA_W 20                 // A row stride, words (20 mod 8 == 4)
#define SB_W 132                // B row stride, words (132 mod 8 == 4)
#define A_BUF_W (256 * SA_W)    // 5120 words
#define OFF_A0 0
#define OFF_A1 A_BUF_W                        // 5120
#define OFF_B  (2 * A_BUF_W)                  // 10240
#define B_WORDS (128 * SB_W)                  // 16896
#define OFF_U  (OFF_B + B_WORDS)              // 27136 (floats)
#define OFF_BI (OFF_U + 128)                  // 27264
#define OFF_SR (OFF_BI + 128)                 // 27392
#define SMEM_WORDS (OFF_SR + 512)             // 27904
#define SMEM_BYTES (SMEM_WORDS * 4)           // 111,616

__global__ void __launch_bounds__(256, 1) k_fused(
    const float* __restrict__ x, const float* __restrict__ bias,
    const float* __restrict__ u, float* __restrict__ out)
{
    extern __shared__ uint32_t smw[];
    const int tid  = threadIdx.x;
    const int lane = tid & 31;
    const int wid  = tid >> 5;
    const int q    = lane >> 2;          // groupID (row within frag)
    const int m    = lane & 3;           // threadID-in-group
    const int mrow = (wid >> 1) * 64;    // row-group base (0..192)
    const int cg   = wid & 1;            // col-group 0..1
    const int ncol = cg * 64;
    const int h    = blockIdx.x & 1;     // N-half
    const int sb0  = blockIdx.x >> 1;
    const int hstep = gridDim.x >> 1;    // CTAs per N-half

    float* usp = reinterpret_cast<float*>(smw + OFF_U);
    float* bip = reinterpret_cast<float*>(smw + OFF_BI);
    if (tid < 128) {
        usp[tid] = u[h * 128 + tid];
        bip[tid] = bias[h * 128 + tid];
    }

    // Resident B half via cp.async: g_Wh rows n = 128h..128h+127, 256 halfs.
    {
        const uint32_t smb = smem_u32(smw);
        #pragma unroll
        for (int i = 0; i < 16; i++) {           // 4096 x 16B
            int idx = i * 256 + tid;
            int n = idx >> 5, c16 = idx & 31;    // 32 x 16B per row
            cp16(smb + (OFF_B + n * SB_W + c16 * 4) * 4,
                 g_Wh + (h * 128 + n) * F_DIM + c16 * 8);
        }
        CP_COMMIT();
    }

    const float4* xg4 = reinterpret_cast<const float4*>(x);
    uint2* gx2 = reinterpret_cast<uint2*>(g_xh);

    // Map a global chunk index g -> its super-block (clamped for tail).
    auto sb_of = [&](int g) {
        int s = sb0 + (g >> 3) * hstep;
        return (s < NSB) ? s : sb0;      // clamp: prefetch beyond end is dead
    };
    // LDG chunk g (k = 32*(g&7) ..) into registers.
    auto ldgA = [&](int g, float4* R) {
        const float4* xg = xg4 + (long)sb_of(g) * 256 * 64;
        const int c_ = g & 7;
        #pragma unroll
        for (int i = 0; i < 8; i++) {
            int idx = i * 256 + tid;
            int r = idx >> 3, c4 = idx & 7;      // 8 float4 per 32-k row
            R[i] = xg[r * 64 + c_ * 8 + c4];
        }
    };
    // Convert + store registers into A buffer; persist fp16 x (parity split).
    auto stsA = [&](const float4* R, int g) {
        uint32_t* ab = smw + ((g & 1) ? OFF_A1 : OFF_A0);
        const int c_ = g & 7;
        const bool wr = (h == (g & 1));
        uint2* gxb = gx2 + (long)sb_of(g) * 256 * 64 + c_ * 8;
        #pragma unroll
        for (int i = 0; i < 8; i++) {
            int idx = i * 256 + tid;
            int r = idx >> 3, c4 = idx & 7;
            __half2 h0 = __floats2half2_rn(R[i].x, R[i].y);
            __half2 h1 = __floats2half2_rn(R[i].z, R[i].w);
            uint2 v;
            v.x = *reinterpret_cast<uint32_t*>(&h0);
            v.y = *reinterpret_cast<uint32_t*>(&h1);
            *reinterpret_cast<uint2*>(ab + r * SA_W + c4 * 2) = v;
            if (wr) gxb[(long)r * 64 + c4] = v;
        }
    };

    float4 R[8];
    ldgA(0, R);          // chunk 0 in flight
    CP_WAIT(0);          // B resident landed
    stsA(R, 0);          // buf0 = chunk 0
    ldgA(1, R);          // R = chunk 1
    __syncthreads();     // publish B, buf0, u/bias

    int gc = 0;          // global chunk index currently being MMA'd
    for (int sb = sb0; sb < NSB; sb += hstep) {
        float acc[4][8][4];
        #pragma unroll
        for (int mt = 0; mt < 4; mt++)
            #pragma unroll
            for (int nt = 0; nt < 8; nt++)
                #pragma unroll
                for (int i = 0; i < 4; i++) acc[mt][nt][i] = 0.f;

        for (int c = 0; c < 8; c++, gc++) {
            // Stage chunk gc+1 (held in R) into its buffer; prefetch gc+2.
            stsA(R, gc + 1);
            ldgA(gc + 2, R);

            const uint32_t* ab = smw + ((gc & 1) ? OFF_A1 : OFF_A0);
            const uint32_t* bb = smw + OFF_B;

            #pragma unroll
            for (int s = 0; s < 2; s++) {        // two k16 steps per chunk
                const int kb = 8 * s;            // word offset within chunk
                uint32_t a[4][4];
                #pragma unroll
                for (int mt = 0; mt < 4; mt++) {
                    const uint32_t* ap = ab + (mrow + mt * 16 + q) * SA_W + kb + m;
                    a[mt][0] = ap[0];
                    a[mt][1] = ap[8 * SA_W];
                    a[mt][2] = ap[4];
                    a[mt][3] = ap[8 * SA_W + 4];
                }
                const uint32_t* bp = bb + (ncol + q) * SB_W + 16 * c + kb + m;
                uint32_t b0[8], b1[8];
                #pragma unroll
                for (int nt = 0; nt < 8; nt++) {
                    b0[nt] = bp[nt * 8 * SB_W];
                    b1[nt] = bp[nt * 8 * SB_W + 4];
                }
                #pragma unroll
                for (int mt = 0; mt < 4; mt++)
                    #pragma unroll
                    for (int nt = 0; nt < 8; nt++) {
                        asm volatile(
                            "mma.sync.aligned.m16n8k16.row.col.f32.f16.f16.f32 "
                            "{%0,%1,%2,%3}, {%4,%5,%6,%7}, {%8,%9}, {%0,%1,%2,%3};"
                            : "+f"(acc[mt][nt][0]), "+f"(acc[mt][nt][1]),
                              "+f"(acc[mt][nt][2]), "+f"(acc[mt][nt][3])
                            : "r"(a[mt][0]), "r"(a[mt][1]),
                              "r"(a[mt][2]), "r"(a[mt][3]),
                              "r"(b0[nt]), "r"(b1[nt]));
                    }
            }
            __syncthreads();   // publish chunk gc+1; retire reads of chunk gc
        }

        // Epilogue: tanh.approx(acc + bias)*u, per-row partial over 128 cols.
        float* sred = reinterpret_cast<float*>(smw + OFF_SR);   // [256][2]
        #pragma unroll
        for (int mt = 0; mt < 4; mt++) {
            float sA = 0.f, sB = 0.f;
            #pragma unroll
            for (int nt = 0; nt < 8; nt++) {
                const int col = ncol + nt * 8 + 2 * m;
                #pragma unroll
                for (int hh = 0; hh < 2; hh++) {
                    const float uu = usp[col + hh], bb2 = bip[col + hh];
                    sA = fmaf(tanh_fast(acc[mt][nt][hh]     + bb2), uu, sA);
                    sB = fmaf(tanh_fast(acc[mt][nt][hh + 2] + bb2), uu, sB);
                }
            }
            sA += __shfl_xor_sync(0xffffffffu, sA, 1);
            sA += __shfl_xor_sync(0xffffffffu, sA, 2);
            sB += __shfl_xor_sync(0xffffffffu, sB, 1);
            sB += __shfl_xor_sync(0xffffffffu, sB, 2);
            if (m == 0) {
                const int r = mrow + mt * 16 + q;
                sred[r * 2 + cg]       = sA;
                sred[(r + 8) * 2 + cg] = sB;
            }
        }
        __syncthreads();
        g_aitp[h][(long)sb * 256 + tid] = sred[tid * 2] + sred[tid * 2 + 1];
        // no trailing sync: next sb's chunk-loop barrier orders sred reuse
    }

    // ================= Phase B: softmax denominators ======================
    global_barrier();
    if (blockIdx.x < B_BATCH) {
        const int b = blockIdx.x;
        float* red = reinterpret_cast<float*>(smw);   // reuse A region
        if (tid == 0) g_cnt[b] = 0;                   // reset tickets
        float s = 0.f;
        for (int i = tid; i < T_LEN; i += 256) {
            const int r = b * T_LEN + i;
            s += expf(g_aitp[0][r] + g_aitp[1][r]);
        }
        red[tid] = s;
        __syncthreads();
        for (int off = 128; off > 0; off >>= 1) {
            if (tid < off) red[tid] += red[tid + off];
            __syncthreads();
        }
        if (tid == 0) g_sum[b] = red[0];
    }
    global_barrier();

    // ================= Phase C: weighted sums (g_xh hot in L2) ===========
    float* w_as = reinterpret_cast<float*>(smw);          // [128]
    float* w_sp = reinterpret_cast<float*>(smw) + 128;    // [8*256]
    __shared__ unsigned s_last;
    for (int task = blockIdx.x; task < NTASK; task += gridDim.x) {
        const int chunk = task & 15, b = task >> 4;
        const int t0 = chunk * 128;
        const float inv = 1.f / (g_sum[b] + 1e-7f);
        if (tid < 128) {
            const int r = b * T_LEN + t0 + tid;
            w_as[tid] = expf(g_aitp[0][r] + g_aitp[1][r]) * inv;
        }
        __syncthreads();

        const int f8 = tid & 31, ts = tid >> 5;
        const uint4* xb = reinterpret_cast<const uint4*>(
            g_xh + ((long)(b * T_LEN + t0)) * F_DIM);
        float r8[8];
        #pragma unroll
        for (int j = 0; j < 8; j++) r8[j] = 0.f;
        #pragma unroll 4
        for (int tt = ts; tt < 128; tt += 8) {
            const uint4 v = xb[tt * 32 + f8];
            const float a = w_as[tt];
            const float2 f0 = __half22float2(*reinterpret_cast<const __half2*>(&v.x));
            const float2 f1 = __half22float2(*reinterpret_cast<const __half2*>(&v.y));
            const float2 f2 = __half22float2(*reinterpret_cast<const __half2*>(&v.z));
            const float2 f3 = __half22float2(*reinterpret_cast<const __half2*>(&v.w));
            r8[0] = fmaf(f0.x, a, r8[0]); r8[1] = fmaf(f0.y, a, r8[1]);
            r8[2] = fmaf(f1.x, a, r8[2]); r8[3] = fmaf(f1.y, a, r8[3]);
            r8[4] = fmaf(f2.x, a, r8[4]); r8[5] = fmaf(f2.y, a, r8[5]);
            r8[6] = fmaf(f3.x, a, r8[6]); r8[7] = fmaf(f3.y, a, r8[7]);
        }
        #pragma unroll
        for (int j = 0; j < 8; j++)
            w_sp[ts * 256 + f8 * 8 + j] = r8[j];
        __syncthreads();
        float s = 0.f;
        #pragma unroll
        for (int t2 = 0; t2 < 8; t2++)
            s += w_sp[t2 * 256 + tid];
        g_part[(chunk * B_BATCH + b) * F_DIM + tid] = s;

        // Completion ticket; last CTA for this b reduces all 16 partials
        // in fixed order c = 0..15 (deterministic).
        __threadfence();
        if (tid == 0) s_last = atomicAdd(&g_cnt[b], 1u);
        __syncthreads();
        if (s_last == 15u) {
            float r = 0.f;
            #pragma unroll
            for (int c = 0; c < 16; c++)
                r += g_part[(c * B_BATCH + b) * F_DIM + tid];
            out[b * F_DIM + tid] = r;
        }
        __syncthreads();   // w_as/w_sp reuse across tasks
    }
}

// ---------------------------------------------------------------------------
extern "C" void kernel_launch(void* const* d_in, const int* in_sizes, int n_in,
                              void* d_out, int out_size)
{
    const float* x    = (const float*)d_in[0];
    const float* W    = (const float*)d_in[1];
    const float* bias = (const float*)d_in[2];
    const float* u    = (const float*)d_in[3];
    float* out = (float*)d_out;

    int sms = 148;
    cudaDeviceGetAttribute(&sms, cudaDevAttrMultiProcessorCount, 0);
    const int grid = sms & ~1;   // even: N-half pairs; all CTAs co-resident

    cudaFuncSetAttribute(k_fused, cudaFuncAttributeMaxDynamicSharedMemorySize, SMEM_BYTES);

    k_wt<<<dim3(8, 8), dim3(32, 8)>>>(W);
    k_fused<<<grid, 256, SMEM_BYTES>>>(x, bias, u, out);
}

// round 15
// speedup vs baseline: 1.2281x; 1.2281x over previous
#include <cuda_runtime.h>
#include <cuda_fp16.h>
#include <cuda_bf16.h>
#include <cstdint>

// Problem constants
#define B_BATCH 64
#define T_LEN   2048
#define F_DIM   256
#define BT      (B_BATCH * T_LEN)   // 131072
#define NSB     (BT / 256)          // 512 super-blocks of 256 rows
#define NCTA    152                 // GB300: 152 SMs, persistent 1 CTA/SM
#define HSTEP   (NCTA / 2)          // 76 CTAs per N-half

// ---------------------------------------------------------------------------
// Scratch (no allocations allowed -> device globals)
// ---------------------------------------------------------------------------
__device__ __half g_Wh[F_DIM * F_DIM];    // W^T fp16: g_Wh[g*256+f] = W[f][g]
__device__ __half g_xh[(long)BT * F_DIM]; // x in fp16 (written in k_ait staging)
__device__ float g_aitp[2][BT];           // per-half partial ait
__device__ float g_sum[B_BATCH];
__device__ float g_part[16 * B_BATCH * F_DIM];
__device__ unsigned g_cnt[B_BATCH];       // wsum completion tickets (reset by softsum)

__device__ __forceinline__ uint32_t smem_u32(const void* p) {
    uint32_t a;
    asm("{ .reg .u64 t; cvta.to.shared.u64 t, %1; cvt.u32.u64 %0, t; }" : "=r"(a) : "l"(p));
    return a;
}
__device__ __forceinline__ void cp16(uint32_t dst, const void* src) {
    asm volatile("cp.async.cg.shared.global [%0], [%1], 16;" :: "r"(dst), "l"(src));
}
#define CP_COMMIT()  asm volatile("cp.async.commit_group;" ::: "memory")
#define CP_WAIT(n)   asm volatile("cp.async.wait_group %0;" :: "n"(n) : "memory")
__device__ __forceinline__ float tanh_fast(float z) {
    float r;
    asm("tanh.approx.f32 %0, %1;" : "=f"(r) : "f"(z));
    return r;
}

// ---------------------------------------------------------------------------
// Phase 0: W -> fp16, transposed to [g][f] (K-major for the B operand)
// ---------------------------------------------------------------------------
__global__ void __launch_bounds__(256) k_wt(const float* __restrict__ W)
{
    __shared__ float tile[32][33];
    const int tx = threadIdx.x, ty = threadIdx.y;
    const int gx = blockIdx.x * 32, gy = blockIdx.y * 32;
    #pragma unroll
    for (int j = ty; j < 32; j += 8)
        tile[j][tx] = W[(gy + j) * F_DIM + gx + tx];
    __syncthreads();
    #pragma unroll
    for (int j = ty; j < 32; j += 8)
        g_Wh[(gx + j) * F_DIM + gy + tx] = __float2half_rn(tile[tx][j]);
}

// ---------------------------------------------------------------------------
// Phase 1 (persistent, N-split, fp16 mma, single-sync overlapped pipeline)
//   CTA h = blockIdx.x & 1 owns cols [128h, 128h+128).
//   B half (fp16, [n][k], word-stride 132) resident in smem, loaded once.
//   A streamed in k=32 chunks; chunk g lives in buffer g&1. Loop body:
//     STS(chunk gc+1) [+ STG fp16 x to g_xh, chunk-parity split] ;
//     LDG(chunk gc+2) ; MMA(chunk gc) ; one syncthreads.
//   8 warps: 4(row) x 2(col) grid of 64x64 tiles; mma.sync m16n8k16 f16.f32.
// ---------------------------------------------------------------------------
#define SA_W 20                 // A row stride, words (20 mod 8 == 4)
#define SB_W 132                // B row stride, words (132 mod 8 == 4)
#define A_BUF_W (256 * SA_W)    // 5120 words
#define OFF_A0 0
#define OFF_A1 A_BUF_W                        // 5120
#define OFF_B  (2 * A_BUF_W)                  // 10240
#define B_WORDS (128 * SB_W)                  // 16896
#define OFF_U  (OFF_B + B_WORDS)              // 27136 (floats)
#define OFF_BI (OFF_U + 128)                  // 27264
#define OFF_SR (OFF_BI + 128)                 // 27392
#define SMEM_WORDS (OFF_SR + 512)             // 27904
#define SMEM_BYTES (SMEM_WORDS * 4)           // 111,616

__global__ void __launch_bounds__(256, 1) k_ait(
    const float* __restrict__ x, const float* __restrict__ bias,
    const float* __restrict__ u)
{
    extern __shared__ uint32_t smw[];
    const int tid  = threadIdx.x;
    const int lane = tid & 31;
    const int wid  = tid >> 5;
    const int q    = lane >> 2;          // groupID (row within frag)
    const int m    = lane & 3;           // threadID-in-group
    const int mrow = (wid >> 1) * 64;    // row-group base (0..192)
    const int cg   = wid & 1;            // col-group 0..1
    const int ncol = cg * 64;
    const int h    = blockIdx.x & 1;     // N-half
    const int sb0  = blockIdx.x >> 1;

    float* usp = reinterpret_cast<float*>(smw + OFF_U);
    float* bip = reinterpret_cast<float*>(smw + OFF_BI);
    if (tid < 128) {
        usp[tid] = u[h * 128 + tid];
        bip[tid] = bias[h * 128 + tid];
    }

    // Resident B half via cp.async: g_Wh rows n = 128h..128h+127, 256 halfs.
    {
        const uint32_t smb = smem_u32(smw);
        #pragma unroll
        for (int i = 0; i < 16; i++) {           // 4096 x 16B
            int idx = i * 256 + tid;
            int n = idx >> 5, c16 = idx & 31;    // 32 x 16B per row
            cp16(smb + (OFF_B + n * SB_W + c16 * 4) * 4,
                 g_Wh + (h * 128 + n) * F_DIM + c16 * 8);
        }
        CP_COMMIT();
    }

    const float4* xg4 = reinterpret_cast<const float4*>(x);
    uint2* gx2 = reinterpret_cast<uint2*>(g_xh);

    // Map a global chunk index g -> its super-block (clamped for tail).
    auto sb_of = [&](int g) {
        int s = sb0 + (g >> 3) * HSTEP;
        return (s < NSB) ? s : sb0;      // clamp: prefetch beyond end is dead
    };
    // LDG chunk g (k = 32*(g&7) ..) into registers.
    auto ldgA = [&](int g, float4* R) {
        const float4* xg = xg4 + (long)sb_of(g) * 256 * 64;
        const int c_ = g & 7;
        #pragma unroll
        for (int i = 0; i < 8; i++) {
            int idx = i * 256 + tid;
            int r = idx >> 3, c4 = idx & 7;      // 8 float4 per 32-k row
            R[i] = xg[r * 64 + c_ * 8 + c4];
        }
    };
    // Convert + store registers into A buffer; persist fp16 x (parity split:
    // exactly one CTA of each half-pair writes g_xh for a given chunk).
    auto stsA = [&](const float4* R, int g) {
        uint32_t* ab = smw + ((g & 1) ? OFF_A1 : OFF_A0);
        const int c_ = g & 7;
        const bool wr = (h == (g & 1));
        uint2* gxb = gx2 + (long)sb_of(g) * 256 * 64 + c_ * 8;
        #pragma unroll
        for (int i = 0; i < 8; i++) {
            int idx = i * 256 + tid;
            int r = idx >> 3, c4 = idx & 7;
            __half2 h0 = __floats2half2_rn(R[i].x, R[i].y);
            __half2 h1 = __floats2half2_rn(R[i].z, R[i].w);
            uint2 v;
            v.x = *reinterpret_cast<uint32_t*>(&h0);
            v.y = *reinterpret_cast<uint32_t*>(&h1);
            *reinterpret_cast<uint2*>(ab + r * SA_W + c4 * 2) = v;
            if (wr) gxb[(long)r * 64 + c4] = v;
        }
    };

    float4 R[8];
    ldgA(0, R);          // chunk 0 in flight
    CP_WAIT(0);          // B resident landed
    stsA(R, 0);          // buf0 = chunk 0
    ldgA(1, R);          // R = chunk 1
    __syncthreads();     // publish B, buf0, u/bias

    int gc = 0;          // global chunk index currently being MMA'd
    for (int sb = sb0; sb < NSB; sb += HSTEP) {
        float acc[4][8][4];
        #pragma unroll
        for (int mt = 0; mt < 4; mt++)
            #pragma unroll
            for (int nt = 0; nt < 8; nt++)
                #pragma unroll
                for (int i = 0; i < 4; i++) acc[mt][nt][i] = 0.f;

        for (int c = 0; c < 8; c++, gc++) {
            // Stage chunk gc+1 (held in R) into its buffer; prefetch gc+2.
            // Safe: buf (gc+1)&1 was last read by mma(gc-1), ordered by the
            // previous iteration's __syncthreads.
            stsA(R, gc + 1);
            ldgA(gc + 2, R);

            const uint32_t* ab = smw + ((gc & 1) ? OFF_A1 : OFF_A0);
            const uint32_t* bb = smw + OFF_B;

            #pragma unroll
            for (int s = 0; s < 2; s++) {        // two k16 steps per chunk
                const int kb = 8 * s;            // word offset within chunk
                uint32_t a[4][4];
                #pragma unroll
                for (int mt = 0; mt < 4; mt++) {
                    const uint32_t* ap = ab + (mrow + mt * 16 + q) * SA_W + kb + m;
                    a[mt][0] = ap[0];
                    a[mt][1] = ap[8 * SA_W];
                    a[mt][2] = ap[4];
                    a[mt][3] = ap[8 * SA_W + 4];
                }
                const uint32_t* bp = bb + (ncol + q) * SB_W + 16 * c + kb + m;
                uint32_t b0[8], b1[8];
                #pragma unroll
                for (int nt = 0; nt < 8; nt++) {
                    b0[nt] = bp[nt * 8 * SB_W];
                    b1[nt] = bp[nt * 8 * SB_W + 4];
                }
                #pragma unroll
                for (int mt = 0; mt < 4; mt++)
                    #pragma unroll
                    for (int nt = 0; nt < 8; nt++) {
                        asm volatile(
                            "mma.sync.aligned.m16n8k16.row.col.f32.f16.f16.f32 "
                            "{%0,%1,%2,%3}, {%4,%5,%6,%7}, {%8,%9}, {%0,%1,%2,%3};"
                            : "+f"(acc[mt][nt][0]), "+f"(acc[mt][nt][1]),
                              "+f"(acc[mt][nt][2]), "+f"(acc[mt][nt][3])
                            : "r"(a[mt][0]), "r"(a[mt][1]),
                              "r"(a[mt][2]), "r"(a[mt][3]),
                              "r"(b0[nt]), "r"(b1[nt]));
                    }
            }
            __syncthreads();   // publish chunk gc+1; retire reads of chunk gc
        }

        // Epilogue: tanh.approx(acc + bias)*u, per-row partial over 128 cols.
        float* sred = reinterpret_cast<float*>(smw + OFF_SR);   // [256][2]
        #pragma unroll
        for (int mt = 0; mt < 4; mt++) {
            float sA = 0.f, sB = 0.f;
            #pragma unroll
            for (int nt = 0; nt < 8; nt++) {
                const int col = ncol + nt * 8 + 2 * m;
                #pragma unroll
                for (int hh = 0; hh < 2; hh++) {
                    const float uu = usp[col + hh], bb2 = bip[col + hh];
                    sA = fmaf(tanh_fast(acc[mt][nt][hh]     + bb2), uu, sA);
                    sB = fmaf(tanh_fast(acc[mt][nt][hh + 2] + bb2), uu, sB);
                }
            }
            sA += __shfl_xor_sync(0xffffffffu, sA, 1);
            sA += __shfl_xor_sync(0xffffffffu, sA, 2);
            sB += __shfl_xor_sync(0xffffffffu, sB, 1);
            sB += __shfl_xor_sync(0xffffffffu, sB, 2);
            if (m == 0) {
                const int r = mrow + mt * 16 + q;
                sred[r * 2 + cg]       = sA;
                sred[(r + 8) * 2 + cg] = sB;
            }
        }
        __syncthreads();
        g_aitp[h][(long)sb * 256 + tid] = sred[tid * 2] + sred[tid * 2 + 1];
        // No trailing sync: every thread reads sred before it can reach the
        // next super-block's first chunk barrier, which precedes any new
        // sred write by 8 more barriers.
    }
}

// ---------------------------------------------------------------------------
// Phase 2: g_sum[b] = sum_t exp(ait[b,t]),  ait = p0 + p1. Resets g_cnt.
// ---------------------------------------------------------------------------
__global__ void __launch_bounds__(256) k_softsum()
{
    __shared__ float red[256];
    const int b = blockIdx.x, tid = threadIdx.x;
    if (tid == 0) g_cnt[b] = 0;          // reset wsum tickets for this replay
    float s = 0.f;
    for (int i = tid; i < T_LEN; i += 256) {
        const int r = b * T_LEN + i;
        s += expf(g_aitp[0][r] + g_aitp[1][r]);
    }
    red[tid] = s;
    __syncthreads();
    for (int off = 128; off > 0; off >>= 1) {
        if (tid < off) red[tid] += red[tid + off];
        __syncthreads();
    }
    if (tid == 0) g_sum[b] = red[0];
}

// ---------------------------------------------------------------------------
// Phase 3: partial weighted sums over 128-t chunks, reading fp16 x (g_xh).
// Loads issued in two front-batched groups of 8 LDG.128 per thread (MLP 8).
// Last-finishing CTA per batch b does the fixed-order 16-way reduction.
// ---------------------------------------------------------------------------
__global__ void __launch_bounds__(256) k_wsum(float* __restrict__ out)
{
    __shared__ float as[128];
    __shared__ float sp[8 * 256];
    __shared__ unsigned last;
    const int chunk = blockIdx.x, b = blockIdx.y, tid = threadIdx.x;
    const int t0 = chunk * 128;
    const float inv = 1.f / (g_sum[b] + 1e-7f);
    if (tid < 128) {
        const int r = b * T_LEN + t0 + tid;
        as[tid] = expf(g_aitp[0][r] + g_aitp[1][r]) * inv;
    }
    __syncthreads();

    const int f8 = tid & 31, ts = tid >> 5;   // f8: 8-half group, ts: t-slice
    const uint4* xb = reinterpret_cast<const uint4*>(
        g_xh + ((long)(b * T_LEN + t0)) * F_DIM) + f8;
    float r8[8];
    #pragma unroll
    for (int j = 0; j < 8; j++) r8[j] = 0.f;

    #pragma unroll
    for (int half = 0; half < 2; half++) {
        // Front-batch 8 independent LDG.128 (tt = ts + (8*half + g)*8).
        uint4 v[8];
        #pragma unroll
        for (int g = 0; g < 8; g++)
            v[g] = xb[(ts + (half * 8 + g) * 8) * 32];
        #pragma unroll
        for (int g = 0; g < 8; g++) {
            const float a = as[ts + (half * 8 + g) * 8];
            const float2 f0 = __half22float2(*reinterpret_cast<const __half2*>(&v[g].x));
            const float2 f1 = __half22float2(*reinterpret_cast<const __half2*>(&v[g].y));
            const float2 f2 = __half22float2(*reinterpret_cast<const __half2*>(&v[g].z));
            const float2 f3 = __half22float2(*reinterpret_cast<const __half2*>(&v[g].w));
            r8[0] = fmaf(f0.x, a, r8[0]); r8[1] = fmaf(f0.y, a, r8[1]);
            r8[2] = fmaf(f1.x, a, r8[2]); r8[3] = fmaf(f1.y, a, r8[3]);
            r8[4] = fmaf(f2.x, a, r8[4]); r8[5] = fmaf(f2.y, a, r8[5]);
            r8[6] = fmaf(f3.x, a, r8[6]); r8[7] = fmaf(f3.y, a, r8[7]);
        }
    }
    #pragma unroll
    for (int j = 0; j < 8; j++)
        sp[ts * 256 + f8 * 8 + j] = r8[j];
    __syncthreads();
    float s = 0.f;
    #pragma unroll
    for (int t2 = 0; t2 < 8; t2++)
        s += sp[t2 * 256 + tid];
    g_part[(chunk * B_BATCH + b) * F_DIM + tid] = s;

    // Completion ticket; last CTA for this b reduces all 16 partials in
    // fixed order c = 0..15 (deterministic regardless of finish order).
    __threadfence();
    if (tid == 0) last = atomicAdd(&g_cnt[b], 1u);
    __syncthreads();
    if (last == 15u) {
        float r = 0.f;
        #pragma unroll
        for (int c = 0; c < 16; c++)
            r += g_part[(c * B_BATCH + b) * F_DIM + tid];
        out[b * F_DIM + tid] = r;
    }
}

// ---------------------------------------------------------------------------
extern "C" void kernel_launch(void* const* d_in, const int* in_sizes, int n_in,
                              void* d_out, int out_size)
{
    const float* x    = (const float*)d_in[0];
    const float* W    = (const float*)d_in[1];
    const float* bias = (const float*)d_in[2];
    const float* u    = (const float*)d_in[3];
    float* out = (float*)d_out;

    cudaFuncSetAttribute(k_ait, cudaFuncAttributeMaxDynamicSharedMemorySize, SMEM_BYTES);

    k_wt<<<dim3(8, 8), dim3(32, 8)>>>(W);
    k_ait<<<NCTA, 256, SMEM_BYTES>>>(x, bias, u);   // persistent, N-split halves
    k_softsum<<<B_BATCH, 256>>>();
    k_wsum<<<dim3(16, B_BATCH), 256>>>(out);        // k_red folded in
}